// round 11
// baseline (speedup 1.0000x reference)
#include <cuda_runtime.h>

#define BATCH  4096
#define IDIM   1024
#define BOND   32
#define ODIM   512

// Tree: 1024 cores -> 128 (prod8) -> 16 (prod8), then fused chain+output.
#define NP1 128
#define NP2 16

__device__ __align__(16) float g_P1[NP1 * BOND * BOND];
__device__ __align__(16) float g_P2[NP2 * BOND * BOND];

// ---------------------------------------------------------------------------
// Transposed store of a float4 covering elements 4t..4t+3 of a 32x32 matrix
// into Bt (pitch 33). Conflict-free.
// ---------------------------------------------------------------------------
__device__ __forceinline__ void transpose_store(float4 v, float* Bt, int t) {
    const int j  = t >> 3;
    const int k0 = (t & 7) * 4;
    Bt[(k0 + 0) * 33 + j] = v.x;
    Bt[(k0 + 1) * 33 + j] = v.y;
    Bt[(k0 + 2) * 33 + j] = v.z;
    Bt[(k0 + 3) * 33 + j] = v.w;
}

// ---------------------------------------------------------------------------
// Block = ordered product of 8 consecutive 32x32 matrices (depth 7).
// Warp w owns rows 4w..4w+3; lane = output column. A rows are uniform
// broadcast LDS.128; B columns read stride-1 from transposed buffer.
// ---------------------------------------------------------------------------
__global__ __launch_bounds__(256) void mps_prod8_kernel(const float* __restrict__ src,
                                                        float* __restrict__ dst) {
    __shared__ float sA[BOND * BOND];
    __shared__ float sBt[2][BOND * 33];

    const int t    = threadIdx.x;
    const int w    = t >> 5;
    const int lane = t & 31;
    const float* base = src + (size_t)blockIdx.x * (8 * BOND * BOND);

    ((float4*)sA)[t] = ((const float4*)base)[t];
    transpose_store(((const float4*)(base + BOND * BOND))[t], sBt[1], t);
    __syncthreads();

    float acc0 = 0.f, acc1 = 0.f, acc2 = 0.f, acc3 = 0.f;

    #pragma unroll
    for (int s = 1; s < 8; ++s) {
        float4 pre;
        if (s + 1 < 8) pre = ((const float4*)(base + (s + 1) * BOND * BOND))[t];

        const float* Bt = sBt[s & 1];
        acc0 = acc1 = acc2 = acc3 = 0.f;

        #pragma unroll
        for (int l4 = 0; l4 < 8; ++l4) {
            const float4 a0 = *(const float4*)(sA + (4 * w + 0) * 32 + 4 * l4);
            const float4 a1 = *(const float4*)(sA + (4 * w + 1) * 32 + 4 * l4);
            const float4 a2 = *(const float4*)(sA + (4 * w + 2) * 32 + 4 * l4);
            const float4 a3 = *(const float4*)(sA + (4 * w + 3) * 32 + 4 * l4);
            const float b0 = Bt[lane * 33 + 4 * l4 + 0];
            const float b1 = Bt[lane * 33 + 4 * l4 + 1];
            const float b2 = Bt[lane * 33 + 4 * l4 + 2];
            const float b3 = Bt[lane * 33 + 4 * l4 + 3];

            acc0 = fmaf(a0.x, b0, acc0); acc0 = fmaf(a0.y, b1, acc0);
            acc0 = fmaf(a0.z, b2, acc0); acc0 = fmaf(a0.w, b3, acc0);
            acc1 = fmaf(a1.x, b0, acc1); acc1 = fmaf(a1.y, b1, acc1);
            acc1 = fmaf(a1.z, b2, acc1); acc1 = fmaf(a1.w, b3, acc1);
            acc2 = fmaf(a2.x, b0, acc2); acc2 = fmaf(a2.y, b1, acc2);
            acc2 = fmaf(a2.z, b2, acc2); acc2 = fmaf(a2.w, b3, acc2);
            acc3 = fmaf(a3.x, b0, acc3); acc3 = fmaf(a3.y, b1, acc3);
            acc3 = fmaf(a3.z, b2, acc3); acc3 = fmaf(a3.w, b3, acc3);
        }
        __syncthreads();
        if (s < 7) {
            sA[(4 * w + 0) * 32 + lane] = acc0;
            sA[(4 * w + 1) * 32 + lane] = acc1;
            sA[(4 * w + 2) * 32 + lane] = acc2;
            sA[(4 * w + 3) * 32 + lane] = acc3;
            transpose_store(pre, sBt[(s + 1) & 1], t);
            __syncthreads();
        }
    }

    float* d = dst + (size_t)blockIdx.x * (BOND * BOND);
    d[(4 * w + 0) * 32 + lane] = acc0;
    d[(4 * w + 1) * 32 + lane] = acc1;
    d[(4 * w + 2) * 32 + lane] = acc2;
    d[(4 * w + 3) * 32 + lane] = acc3;
}

// ---------------------------------------------------------------------------
// Fused final kernel: 128 blocks x 1024 threads, 32 batch rows per block
// (one warp per row). Each block:
//   1. issues its 32 input-row loads (8 LDG.128/lane) and stages the 16 P2
//      matrices (64KB) into smem,
//   2. computes per-row product p (warp reduce) while warp 0 runs the
//      16-step vector chain v = ones @ P2_0 @ ... @ P2_15 from smem,
//   3. 512 threads compute sw = v @ projection (once per block),
//   4. all warps write out[row,:] = p * sw + bias.
// Redundant chain per block (~1100 cyc) trades for 2 fewer kernel launches.
// ---------------------------------------------------------------------------
// dynamic smem layout: sP[16*1024] | sw[512] | sv[32]
#define SMEM_FLOATS (NP2 * 1024 + ODIM + BOND)

__global__ __launch_bounds__(1024) void mps_output_fused_kernel(
        const float* __restrict__ inputs,
        const float* __restrict__ proj,
        const float* __restrict__ bias,
        float* __restrict__ out) {
    extern __shared__ float sP[];
    float* sw = sP + NP2 * 1024;
    float* sv = sw + ODIM;

    const int tid  = threadIdx.x;
    const int wid  = tid >> 5;
    const int lane = tid & 31;
    const int b    = blockIdx.x * 32 + wid;

    // 1a. input row loads (deep MLP, independent of staging)
    const float4* row = (const float4*)(inputs + (size_t)b * IDIM);
    float4 r[8];
    #pragma unroll
    for (int i = 0; i < 8; ++i) r[i] = row[lane + 32 * i];

    // 1b. stage P2: 1024 threads * 4 float4 = 4096 float4 = 64KB
    {
        const float4* g4 = (const float4*)g_P2;
        float4*       s4 = (float4*)sP;
        #pragma unroll
        for (int i = 0; i < 4; ++i) s4[tid + 1024 * i] = g4[tid + 1024 * i];
    }

    // 2a. per-row product (releases r[] registers before the barrier)
    float p0 = (r[0].x * r[0].y) * (r[0].z * r[0].w);
    float p1 = (r[1].x * r[1].y) * (r[1].z * r[1].w);
    float p2 = (r[2].x * r[2].y) * (r[2].z * r[2].w);
    float p3 = (r[3].x * r[3].y) * (r[3].z * r[3].w);
    float p4 = (r[4].x * r[4].y) * (r[4].z * r[4].w);
    float p5 = (r[5].x * r[5].y) * (r[5].z * r[5].w);
    float p6 = (r[6].x * r[6].y) * (r[6].z * r[6].w);
    float p7 = (r[7].x * r[7].y) * (r[7].z * r[7].w);
    float p  = ((p0 * p1) * (p2 * p3)) * ((p4 * p5) * (p6 * p7));
    #pragma unroll
    for (int off = 16; off; off >>= 1)
        p *= __shfl_xor_sync(0xffffffffu, p, off);

    __syncthreads();           // staging visible

    // 2b. warp 0: 16-step vector chain from smem (broadcast LDS)
    if (wid == 0) {
        float v = 1.0f;
        #pragma unroll
        for (int c = 0; c < NP2; ++c) {
            const float* P = sP + c * 1024;
            float a0 = 0.f, a1 = 0.f, a2 = 0.f, a3 = 0.f;
            #pragma unroll
            for (int j = 0; j < 8; ++j) {
                a0 = fmaf(__shfl_sync(0xffffffffu, v, j),      P[j * 32 + lane],        a0);
                a1 = fmaf(__shfl_sync(0xffffffffu, v, j + 8),  P[(j + 8) * 32 + lane],  a1);
                a2 = fmaf(__shfl_sync(0xffffffffu, v, j + 16), P[(j + 16) * 32 + lane], a2);
                a3 = fmaf(__shfl_sync(0xffffffffu, v, j + 24), P[(j + 24) * 32 + lane], a3);
            }
            v = (a0 + a1) + (a2 + a3);
        }
        sv[lane] = v;
    }
    __syncthreads();           // sv ready

    // 3. w = v @ projection (512 threads; 32 outstanding LDGs hide L2 latency)
    if (tid < ODIM) {
        float a0 = 0.f, a1 = 0.f, a2 = 0.f, a3 = 0.f;
        #pragma unroll
        for (int j = 0; j < 8; ++j) {
            a0 = fmaf(sv[j],      proj[(j)      * ODIM + tid], a0);
            a1 = fmaf(sv[j + 8],  proj[(j + 8)  * ODIM + tid], a1);
            a2 = fmaf(sv[j + 16], proj[(j + 16) * ODIM + tid], a2);
            a3 = fmaf(sv[j + 24], proj[(j + 24) * ODIM + tid], a3);
        }
        sw[tid] = (a0 + a1) + (a2 + a3);
    }
    __syncthreads();           // sw ready

    // 4. write out[b,:] = p * sw + bias
    const float4* w4 = (const float4*)sw;
    const float4* b4 = (const float4*)bias;
    float4*       o4 = (float4*)(out + (size_t)b * ODIM);
    #pragma unroll
    for (int i = 0; i < 4; ++i) {
        const float4 wv = w4[lane + 32 * i];
        const float4 bv = b4[lane + 32 * i];
        float4 ov;
        ov.x = fmaf(p, wv.x, bv.x);
        ov.y = fmaf(p, wv.y, bv.y);
        ov.z = fmaf(p, wv.z, bv.z);
        ov.w = fmaf(p, wv.w, bv.w);
        o4[lane + 32 * i] = ov;
    }
}

// ---------------------------------------------------------------------------
extern "C" void kernel_launch(void* const* d_in, const int* in_sizes, int n_in,
                              void* d_out, int out_size) {
    const float* inputs = (const float*)d_in[0];
    const float* cores  = (const float*)d_in[1];
    const float* proj   = (const float*)d_in[2];
    const float* bias   = (const float*)d_in[3];
    float* out = (float*)d_out;

    float* p1; cudaGetSymbolAddress((void**)&p1, g_P1);
    float* p2; cudaGetSymbolAddress((void**)&p2, g_P2);

    // Idempotent, capture-safe, called unconditionally (no static guards).
    cudaFuncSetAttribute(mps_output_fused_kernel,
                         cudaFuncAttributeMaxDynamicSharedMemorySize,
                         SMEM_FLOATS * (int)sizeof(float));

    mps_prod8_kernel<<<NP1, 256>>>(cores, p1);   // 1024 -> 128
    mps_prod8_kernel<<<NP2, 256>>>(p1, p2);      // 128  -> 16
    mps_output_fused_kernel<<<BATCH / 32, 1024, SMEM_FLOATS * sizeof(float)>>>(
        inputs, proj, bias, out);
}